// round 16
// baseline (speedup 1.0000x reference)
#include <cuda_runtime.h>
#include <cuda_bf16.h>
#include <stdint.h>
#include <math.h>

#define L_SEQ 4096
#define BATCH 2
#define HID   1024
#define DHEAD 64
#define CHUNK 64
#define NCHUNK (L_SEQ / CHUNK)
#define ROWS  (BATCH * L_SEQ)
#define GAMMA_F 0.96875f
#define LOG2_GAMMA (-0.04580368961f)
#define SDEPTH 16   // gamma^(64*16) ~ 7e-15: below fp32 noise

// Scratch (__device__ globals; no allocations allowed)
__device__ __nv_bfloat16 g_Xh[ROWS * HID];
__device__ __nv_bfloat16 g_Xl[ROWS * HID];
__device__ __nv_bfloat16 g_Wth[3 * DHEAD * HID];   // [which][n][k]
__device__ __nv_bfloat16 g_Wtl[3 * DHEAD * HID];
__device__ float g_Q[ROWS * DHEAD];
__device__ float g_K[ROWS * DHEAD];
__device__ float g_V[ROWS * DHEAD];
__device__ float g_A[BATCH * NCHUNK * DHEAD * DHEAD];
__device__ float g_S[BATCH * NCHUNK * DHEAD * DHEAD];

#define MMA16816(d, a, b)                                                   \
    asm volatile(                                                           \
        "mma.sync.aligned.m16n8k16.row.col.f32.bf16.bf16.f32 "              \
        "{%0,%1,%2,%3}, {%4,%5,%6,%7}, {%8,%9}, {%0,%1,%2,%3};\n"           \
        : "+f"(d[0]), "+f"(d[1]), "+f"(d[2]), "+f"(d[3])                    \
        : "r"(a[0]), "r"(a[1]), "r"(a[2]), "r"(a[3]), "r"(b[0]), "r"(b[1]))

// ---------------------------------------------------------------------------
// P0: split X (fp32 -> bf16 hi/lo) and transpose+split W, one launch.
// ---------------------------------------------------------------------------
__global__ __launch_bounds__(256) void split_kernel(
    const float* __restrict__ X,
    const float* __restrict__ WQ,
    const float* __restrict__ WK,
    const float* __restrict__ WV) {
    if (blockIdx.x < 4096) {
        const size_t tid = (size_t)blockIdx.x * 256 + threadIdx.x;
        const float4* p = (const float4*)X + tid * 2;
        float4 a = p[0], b = p[1];
        float v[8] = {a.x, a.y, a.z, a.w, b.x, b.y, b.z, b.w};
        __nv_bfloat162 hh[4], ll[4];
#pragma unroll
        for (int i = 0; i < 4; i++) {
            __nv_bfloat16 h0 = __float2bfloat16(v[2 * i + 0]);
            __nv_bfloat16 h1 = __float2bfloat16(v[2 * i + 1]);
            hh[i] = __nv_bfloat162(h0, h1);
            ll[i] = __nv_bfloat162(__float2bfloat16(v[2 * i + 0] - __bfloat162float(h0)),
                                   __float2bfloat16(v[2 * i + 1] - __bfloat162float(h1)));
        }
        *(uint4*)&g_Xh[tid * 8] = *(uint4*)hh;
        *(uint4*)&g_Xl[tid * 8] = *(uint4*)ll;
    } else {
        int idx = (blockIdx.x - 4096) * 256 + threadIdx.x;
#pragma unroll
        for (int e = 0; e < 4; e++, idx += 49152) {
            const int which = idx >> 16;
            const int rem   = idx & 65535;
            const int n = rem >> 10, k = rem & 1023;
            const float* W = (which == 0) ? WQ : ((which == 1) ? WK : WV);
            const float v = W[(size_t)k * DHEAD + n];
            __nv_bfloat16 h = __float2bfloat16(v);
            g_Wth[idx] = h;
            g_Wtl[idx] = __float2bfloat16(v - __bfloat162float(h));
        }
    }
}

// ---------------------------------------------------------------------------
// P1: projection (unchanged — near mma.sync roofline).
// ---------------------------------------------------------------------------
__global__ __launch_bounds__(256) void proj_mma_kernel() {
    const int which = blockIdx.y;
    float* __restrict__ Out = (which == 0) ? g_Q : ((which == 1) ? g_K : g_V);
    const __nv_bfloat16* __restrict__ Wh = g_Wth + (size_t)which * DHEAD * HID;
    const __nv_bfloat16* __restrict__ Wl = g_Wtl + (size_t)which * DHEAD * HID;

    __shared__ __nv_bfloat16 Ah[64][72];
    __shared__ __nv_bfloat16 Al[64][72];
    __shared__ __nv_bfloat16 Bh[64][72];
    __shared__ __nv_bfloat16 Bl[64][72];

    const int t    = threadIdx.x;
    const int warp = t >> 5, lane = t & 31;
    const int grp  = lane >> 2, tig = lane & 3;
    const int wm   = warp >> 1;
    const int wn   = warp & 1;
    const int m0   = blockIdx.x * 64;

    const int r0 = t >> 3, c8 = (t & 7) * 8;

    uint4 rXh[2], rXl[2], rWh[2], rWl[2];

    auto issue = [&](int k0) {
#pragma unroll
        for (int e = 0; e < 2; e++) {
            const int row = r0 + e * 32;
            const size_t xo = (size_t)(m0 + row) * HID + k0 + c8;
            rXh[e] = *(const uint4*)(g_Xh + xo);
            rXl[e] = *(const uint4*)(g_Xl + xo);
            const size_t wo = (size_t)row * HID + k0 + c8;
            rWh[e] = *(const uint4*)(Wh + wo);
            rWl[e] = *(const uint4*)(Wl + wo);
        }
    };

    float acc[4][4];
#pragma unroll
    for (int nt = 0; nt < 4; nt++)
#pragma unroll
        for (int c = 0; c < 4; c++) acc[nt][c] = 0.0f;

    issue(0);
    for (int k0 = 0; k0 < HID; k0 += 64) {
#pragma unroll
        for (int e = 0; e < 2; e++) {
            const int row = r0 + e * 32;
            *(uint4*)&Ah[row][c8] = rXh[e];
            *(uint4*)&Al[row][c8] = rXl[e];
            *(uint4*)&Bh[row][c8] = rWh[e];
            *(uint4*)&Bl[row][c8] = rWl[e];
        }
        __syncthreads();
        if (k0 + 64 < HID) issue(k0 + 64);

#pragma unroll
        for (int ks = 0; ks < 64; ks += 16) {
            const int r = wm * 16 + grp;
            const int c = ks + tig * 2;
            uint32_t ah[4], al[4];
            ah[0] = *(const uint32_t*)&Ah[r][c];
            ah[1] = *(const uint32_t*)&Ah[r + 8][c];
            ah[2] = *(const uint32_t*)&Ah[r][c + 8];
            ah[3] = *(const uint32_t*)&Ah[r + 8][c + 8];
            al[0] = *(const uint32_t*)&Al[r][c];
            al[1] = *(const uint32_t*)&Al[r + 8][c];
            al[2] = *(const uint32_t*)&Al[r][c + 8];
            al[3] = *(const uint32_t*)&Al[r + 8][c + 8];
#pragma unroll
            for (int nt = 0; nt < 4; nt++) {
                const int n = wn * 32 + nt * 8 + grp;
                uint32_t bh[2], bl[2];
                bh[0] = *(const uint32_t*)&Bh[n][c];
                bh[1] = *(const uint32_t*)&Bh[n][c + 8];
                bl[0] = *(const uint32_t*)&Bl[n][c];
                bl[1] = *(const uint32_t*)&Bl[n][c + 8];
                MMA16816(acc[nt], ah, bh);
                MMA16816(acc[nt], ah, bl);
                MMA16816(acc[nt], al, bh);
            }
        }
        __syncthreads();
    }

    const bool dox  = (which < 2);
    const bool down = (which == 1);
#pragma unroll
    for (int nt = 0; nt < 4; nt++) {
        const int col = wn * 32 + nt * 8 + tig * 2;
        const int h   = col >> 1;
        float lsv = 0.f, invf = 0.f;
        if (dox) {
            lsv  = __log2f(((float)col + 25.6f) / 89.6f);
            invf = exp2f((float)h * (-13.287712379549449f / 32.0f));
        }
#pragma unroll
        for (int half = 0; half < 2; half++) {
            const int rr = m0 + wm * 16 + grp + half * 8;
            float x0 = acc[nt][half * 2 + 0];
            float x1 = acc[nt][half * 2 + 1];
            if (dox) {
                const float pos = (float)(rr & (L_SEQ - 1));
                float e = lsv * pos * (1.0f / 512.0f);
                if (down) e = -e;
                const float sc = exp2f(e);
                float s, cg;
                sincosf(pos * invf, &s, &cg);
                s *= sc; cg *= sc;
                const float y0 = x0 * cg - x1 * s;
                const float y1 = x1 * cg + x0 * s;
                x0 = y0; x1 = y1;
            }
            *(float2*)(Out + (size_t)rr * DHEAD + col) = make_float2(x0, x1);
        }
    }
}

// ---------------------------------------------------------------------------
// P2: per-chunk decayed A_j = (decayed K)^T V, z-split over 4 column quarters.
// ---------------------------------------------------------------------------
__global__ __launch_bounds__(256) void chunk_stats_kernel() {
    const int j  = blockIdx.x;
    const int b  = blockIdx.y;
    const int cb = blockIdx.z * 16;
    __shared__ float Ks[CHUNK][DHEAD];
    __shared__ float Vs[CHUNK][17];

    const int t = threadIdx.x;
    const size_t base = (size_t)(b * L_SEQ + j * CHUNK) * DHEAD;
    for (int i = t; i < CHUNK * DHEAD; i += 256) {
        const int r = i >> 6, d = i & 63;
        const float w = exp2f((float)(CHUNK - 1 - r) * LOG2_GAMMA);
        Ks[r][d] = g_K[base + i] * w;
    }
    for (int i = t; i < CHUNK * 16; i += 256) {
        const int r = i >> 4, d = i & 15;
        Vs[r][d] = g_V[base + r * DHEAD + cb + d];
    }
    __syncthreads();

    const int ty = t >> 4, tx = t & 15;
    float acc[4] = {0.f, 0.f, 0.f, 0.f};

    for (int r = 0; r < CHUNK; r++) {
        const float v = Vs[r][tx];
#pragma unroll
        for (int i = 0; i < 4; i++)
            acc[i] = fmaf(Ks[r][ty * 4 + i], v, acc[i]);
    }

    float* __restrict__ Ap = g_A + (size_t)(b * NCHUNK + j) * DHEAD * DHEAD;
#pragma unroll
    for (int i = 0; i < 4; i++)
        Ap[(ty * 4 + i) * DHEAD + cb + tx] = acc[i];
}

// ---------------------------------------------------------------------------
// P2b: windowed scan as banded combination. Block = (32-elem slice, batch).
// Each A element is read ONCE; all 64 S_j for the slice computed from smem.
// ---------------------------------------------------------------------------
__global__ __launch_bounds__(256) void wscan_kernel() {
    const int es = blockIdx.x;       // 0..127: 32-elem slice
    const int b  = blockIdx.y;
    __shared__ float As[NCHUNK][32];

    const int t = threadIdx.x;
    const float* __restrict__ Ab = g_A + (size_t)b * NCHUNK * 4096 + es * 32;
#pragma unroll
    for (int k = 0; k < 8; k++) {
        const int idx = t + k * 256;
        As[idx >> 5][idx & 31] = Ab[(size_t)(idx >> 5) * 4096 + (idx & 31)];
    }
    __syncthreads();

    const float gC = exp2f((float)CHUNK * LOG2_GAMMA);
    float* __restrict__ Sb = g_S + (size_t)b * NCHUNK * 4096 + es * 32;
#pragma unroll
    for (int k = 0; k < 8; k++) {
        const int idx = t + k * 256;
        const int j = idx >> 5, e = idx & 31;     // j uniform per warp
        float s = 0.0f, w = 1.0f;
        const int dmax = (j < SDEPTH) ? j : SDEPTH;
        for (int d = 1; d <= dmax; d++) {
            s = fmaf(w, As[j - d][e], s);
            w *= gC;
        }
        Sb[(size_t)j * 4096 + e] = s;
    }
}

// ---------------------------------------------------------------------------
// P3: per-chunk output on TENSOR CORES.  Row-split z=2, 512 threads (16 warps).
// S precomputed (flat load).  All GEMMs via 3-pass bf16 split mma.
// ---------------------------------------------------------------------------
struct OutSmem {
    __nv_bfloat16 Qh[32][72], Ql[32][72];   // Q rows rb..rb+31      [m][k]
    __nv_bfloat16 Kh[64][72], Kl[64][72];   // K rows (B for P)      [n][k]
    __nv_bfloat16 Vh[64][72], Vl[64][72];   // V^T (B for O1)        [n=d][k=r']
    __nv_bfloat16 Sh[64][72], Sl[64][72];   // S^T (B for O2)        [n=dout][k=d1]
    __nv_bfloat16 Ph[32][72], Pl[32][72];   // masked P (A for O1)   [m][k=r']
};

__global__ __launch_bounds__(512) void out_mma_kernel(float* __restrict__ O) {
    extern __shared__ char smem_raw[];
    OutSmem* sm = (OutSmem*)smem_raw;

    const int j  = blockIdx.x;
    const int b  = blockIdx.y;
    const int rb = blockIdx.z * 32;          // row base within chunk

    const int t    = threadIdx.x;
    const int warp = t >> 5, lane = t & 31;
    const int grp  = lane >> 2, tig = lane & 3;
    const int wm   = warp >> 3;              // 0..1 -> 16-row tile
    const int wn   = warp & 7;               // 0..7 -> one 8-col n-tile

    const size_t cbase = (size_t)(b * L_SEQ + j * CHUNK) * DHEAD;

    // ---- fills (512 threads) ----
    {   // Q rows rb..rb+31: 4 elems/thread
        const int r = t >> 4, d0 = (t & 15) * 4;
        float4 u = *(const float4*)(g_Q + cbase + (rb + r) * DHEAD + d0);
        float v[4] = {u.x, u.y, u.z, u.w};
#pragma unroll
        for (int e = 0; e < 4; e++) {
            __nv_bfloat16 h = __float2bfloat16(v[e]);
            sm->Qh[r][d0 + e] = h;
            sm->Ql[r][d0 + e] = __float2bfloat16(v[e] - __bfloat162float(h));
        }
    }
    {   // K (natural), V (transposed), S (transposed): 8 elems/thread each
        const int r = t >> 3, d0 = (t & 7) * 8;
#pragma unroll
        for (int q4 = 0; q4 < 2; q4++) {
            float4 u = *(const float4*)(g_K + cbase + r * DHEAD + d0 + q4 * 4);
            float v[4] = {u.x, u.y, u.z, u.w};
#pragma unroll
            for (int e = 0; e < 4; e++) {
                __nv_bfloat16 h = __float2bfloat16(v[e]);
                sm->Kh[r][d0 + q4 * 4 + e] = h;
                sm->Kl[r][d0 + q4 * 4 + e] = __float2bfloat16(v[e] - __bfloat162float(h));
            }
        }
#pragma unroll
        for (int q4 = 0; q4 < 2; q4++) {
            float4 u = *(const float4*)(g_V + cbase + r * DHEAD + d0 + q4 * 4);
            float v[4] = {u.x, u.y, u.z, u.w};
#pragma unroll
            for (int e = 0; e < 4; e++) {
                __nv_bfloat16 h = __float2bfloat16(v[e]);
                sm->Vh[d0 + q4 * 4 + e][r] = h;      // transposed
                sm->Vl[d0 + q4 * 4 + e][r] = __float2bfloat16(v[e] - __bfloat162float(h));
            }
        }
        const float* __restrict__ Sp = g_S + (size_t)(b * NCHUNK + j) * 4096;
#pragma unroll
        for (int q4 = 0; q4 < 2; q4++) {
            float4 u = *(const float4*)(Sp + r * DHEAD + d0 + q4 * 4);
            float v[4] = {u.x, u.y, u.z, u.w};
#pragma unroll
            for (int e = 0; e < 4; e++) {
                __nv_bfloat16 h = __float2bfloat16(v[e]);
                sm->Sh[d0 + q4 * 4 + e][r] = h;      // transposed
                sm->Sl[d0 + q4 * 4 + e][r] = __float2bfloat16(v[e] - __bfloat162float(h));
            }
        }
    }
    __syncthreads();

    // ---- 3-pass gemm: acc[4] += A[32 x 64k] * B[64n x 64k]^T (one n-tile) ----
    auto gemm3 = [&](const __nv_bfloat16 (*Ah_)[72], const __nv_bfloat16 (*Al_)[72],
                     const __nv_bfloat16 (*Bh_)[72], const __nv_bfloat16 (*Bl_)[72],
                     float acc[4]) {
#pragma unroll
        for (int pass = 0; pass < 3; pass++) {
            const __nv_bfloat16 (*Ap)[72] = (pass == 2) ? Al_ : Ah_;
            const __nv_bfloat16 (*Bp)[72] = (pass == 1) ? Bl_ : Bh_;
#pragma unroll
            for (int k0 = 0; k0 < 64; k0 += 16) {
                const int c = k0 + tig * 2;
                const int r = wm * 16 + grp;
                uint32_t a[4];
                a[0] = *(const uint32_t*)&Ap[r][c];
                a[1] = *(const uint32_t*)&Ap[r + 8][c];
                a[2] = *(const uint32_t*)&Ap[r][c + 8];
                a[3] = *(const uint32_t*)&Ap[r + 8][c + 8];
                const int n = wn * 8 + grp;
                uint32_t bb[2];
                bb[0] = *(const uint32_t*)&Bp[n][c];
                bb[1] = *(const uint32_t*)&Bp[n][c + 8];
                MMA16816(acc, a, bb);
            }
        }
    };

    // ---- P = Q K^T, mask+decay in regs, split to smem ----
    {
        float pc[4] = {0.f, 0.f, 0.f, 0.f};
        gemm3(sm->Qh, sm->Ql, sm->Kh, sm->Kl, pc);
#pragma unroll
        for (int e = 0; e < 4; e++) {
            const int rl = wm * 16 + grp + 8 * (e >> 1);      // local row
            const int rg = rb + rl;                           // global row in chunk
            const int rp = wn * 8 + tig * 2 + (e & 1);
            const int m  = rg - rp;
            const float f = (m >= 0) ? exp2f((float)m * LOG2_GAMMA) : 0.0f;
            const float pv = pc[e] * f;
            __nv_bfloat16 h = __float2bfloat16(pv);
            sm->Ph[rl][rp] = h;
            sm->Pl[rl][rp] = __float2bfloat16(pv - __bfloat162float(h));
        }
    }
    __syncthreads();

    // ---- O1 = P @ V^T-layout,  O2 = Q @ S^T-layout ----
    float oc[4] = {0.f, 0.f, 0.f, 0.f};
    float qc[4] = {0.f, 0.f, 0.f, 0.f};
    gemm3(sm->Ph, sm->Pl, sm->Vh, sm->Vl, oc);
    gemm3(sm->Qh, sm->Ql, sm->Sh, sm->Sl, qc);

    // ---- epilogue: O = O1 + g^(rg+1) * O2 ----
    const int col = wn * 8 + tig * 2;
#pragma unroll
    for (int half = 0; half < 2; half++) {
        const int rg = rb + wm * 16 + grp + 8 * half;
        const float g = exp2f((float)(rg + 1) * LOG2_GAMMA);
        const size_t orow = cbase + (size_t)rg * DHEAD;
        float2 val;
        val.x = oc[half * 2 + 0] + g * qc[half * 2 + 0];
        val.y = oc[half * 2 + 1] + g * qc[half * 2 + 1];
        *(float2*)(O + orow + col) = val;
    }
}

// ---------------------------------------------------------------------------
extern "C" void kernel_launch(void* const* d_in, const int* in_sizes, int n_in,
                              void* d_out, int out_size) {
    const float* X  = (const float*)d_in[0];
    const float* WQ = (const float*)d_in[1];
    const float* WK = (const float*)d_in[2];
    const float* WV = (const float*)d_in[3];
    float* O = (float*)d_out;

    cudaFuncSetAttribute(out_mma_kernel,
                         cudaFuncAttributeMaxDynamicSharedMemorySize,
                         (int)sizeof(OutSmem));

    split_kernel<<<4288, 256>>>(X, WQ, WK, WV);
    proj_mma_kernel<<<dim3(ROWS / 64, 3), 256>>>();
    chunk_stats_kernel<<<dim3(NCHUNK, BATCH, 4), 256>>>();
    wscan_kernel<<<dim3(128, BATCH), 256>>>();
    out_mma_kernel<<<dim3(NCHUNK, BATCH, 2), 512, sizeof(OutSmem)>>>(O);
}